// round 2
// baseline (speedup 1.0000x reference)
#include <cuda_runtime.h>
#include <cuda_bf16.h>
#include <cstdint>

// StableMoEGate: logits = x[T,H] @ W[E,H]^T ; softmax over E=64; top-2; renorm softmax.
// Outputs concatenated into float32 d_out: [scores 2T][idx-as-float 2T][aux 1].

#define T_TOKENS 16384
#define H_DIM    4096
#define E_EXP    64
#define BM       128            // tokens per block
#define BK       32             // k-slice per stage
#define NSTAGE   (H_DIM / BK)   // 128

__device__ float g_logits[T_TOKENS * E_EXP];   // 4 MB scratch (static device mem: allowed)

__device__ __forceinline__ void fma2(unsigned long long &acc,
                                     unsigned long long a,
                                     unsigned long long b) {
    // packed dual-fp32 FMA (sm_100+), 2x FFMA throughput
    asm("fma.rn.f32x2 %0, %1, %2, %3;" : "=l"(acc) : "l"(a), "l"(b), "l"(acc));
}

__device__ __forceinline__ void cp16(void* smem, const void* gmem) {
    unsigned saddr = (unsigned)__cvta_generic_to_shared(smem);
    asm volatile("cp.async.cg.shared.global [%0], [%1], 16;" :: "r"(saddr), "l"(gmem));
}

__device__ __forceinline__ float flo(unsigned long long v) {
    return __uint_as_float((unsigned)v);
}
__device__ __forceinline__ float fhi(unsigned long long v) {
    return __uint_as_float((unsigned)(v >> 32));
}

// ---------------------------------------------------------------------------
// Kernel 1: logits GEMM. Block = 128 tokens x 64 experts. Thread = 8 tok x 4 exp,
// accumulated as f32x2 pairs over k (even/odd lanes), reduced at the end.
// ---------------------------------------------------------------------------
__global__ void __launch_bounds__(256, 1)
gate_gemm(const float* __restrict__ x, const float* __restrict__ W) {
    __shared__ __align__(16) float xs[2][BM][BK];           // 32 KB, natural row layout (cp.async)
    __shared__ __align__(16) float wt[2][BK / 2][E_EXP][2]; // 16 KB, k-pair-major transposed W

    const int tid = threadIdx.x;
    const int tx  = tid & 15;        // expert group: e0 = tx*4
    const int ty  = tid >> 4;        // token  group: t0 = ty*8
    const int t0  = ty * 8;
    const int e0  = tx * 4;
    const int tb  = blockIdx.x * BM;

    unsigned long long acc[8][4];
#pragma unroll
    for (int j = 0; j < 8; ++j)
#pragma unroll
        for (int i = 0; i < 4; ++i) acc[j][i] = 0ULL;

    // ---- prologue: stage 0 ----
    {
#pragma unroll
        for (int r = 0; r < 4; ++r) {
            int id = tid + 256 * r;
            int t = id >> 3, c = id & 7;
            cp16(&xs[0][t][4 * c], &x[(size_t)(tb + t) * H_DIM + 4 * c]);
        }
        asm volatile("cp.async.commit_group;" ::: "memory");
        float4 wr[2];
#pragma unroll
        for (int r = 0; r < 2; ++r) {
            int id = tid + 256 * r;
            int e = id >> 3, c = id & 7;
            wr[r] = *reinterpret_cast<const float4*>(&W[(size_t)e * H_DIM + 4 * c]);
        }
#pragma unroll
        for (int r = 0; r < 2; ++r) {
            int id = tid + 256 * r;
            int e = id >> 3, c = id & 7;
            wt[0][2 * c    ][e][0] = wr[r].x; wt[0][2 * c    ][e][1] = wr[r].y;
            wt[0][2 * c + 1][e][0] = wr[r].z; wt[0][2 * c + 1][e][1] = wr[r].w;
        }
        asm volatile("cp.async.wait_group 0;" ::: "memory");
        __syncthreads();
    }

    for (int s = 0; s < NSTAGE; ++s) {
        const int cb = s & 1, nb = cb ^ 1;
        const bool has_next = (s + 1) < NSTAGE;
        float4 wr[2];

        if (has_next) {
            const int h = (s + 1) * BK;
#pragma unroll
            for (int r = 0; r < 4; ++r) {
                int id = tid + 256 * r;
                int t = id >> 3, c = id & 7;
                cp16(&xs[nb][t][4 * c], &x[(size_t)(tb + t) * H_DIM + h + 4 * c]);
            }
            asm volatile("cp.async.commit_group;" ::: "memory");
#pragma unroll
            for (int r = 0; r < 2; ++r) {
                int id = tid + 256 * r;
                int e = id >> 3, c = id & 7;
                wr[r] = *reinterpret_cast<const float4*>(&W[(size_t)e * H_DIM + h + 4 * c]);
            }
        }

        // ---- compute current stage ----
#pragma unroll
        for (int kp = 0; kp < BK / 2; ++kp) {
            unsigned long long wv[4];
            ulonglong2 w01 = *reinterpret_cast<const ulonglong2*>(&wt[cb][kp][e0][0]);
            ulonglong2 w23 = *reinterpret_cast<const ulonglong2*>(&wt[cb][kp][e0 + 2][0]);
            wv[0] = w01.x; wv[1] = w01.y; wv[2] = w23.x; wv[3] = w23.y;
            unsigned long long xv[8];
#pragma unroll
            for (int j = 0; j < 8; ++j)
                xv[j] = *reinterpret_cast<const unsigned long long*>(&xs[cb][t0 + j][2 * kp]);
#pragma unroll
            for (int j = 0; j < 8; ++j)
#pragma unroll
                for (int i = 0; i < 4; ++i)
                    fma2(acc[j][i], xv[j], wv[i]);
        }

        if (has_next) {
#pragma unroll
            for (int r = 0; r < 2; ++r) {
                int id = tid + 256 * r;
                int e = id >> 3, c = id & 7;
                wt[nb][2 * c    ][e][0] = wr[r].x; wt[nb][2 * c    ][e][1] = wr[r].y;
                wt[nb][2 * c + 1][e][0] = wr[r].z; wt[nb][2 * c + 1][e][1] = wr[r].w;
            }
            asm volatile("cp.async.wait_group 0;" ::: "memory");
        }
        __syncthreads();
    }

    // ---- epilogue: reduce f32x2 halves, write logits ----
#pragma unroll
    for (int j = 0; j < 8; ++j) {
        float4 o;
        o.x = flo(acc[j][0]) + fhi(acc[j][0]);
        o.y = flo(acc[j][1]) + fhi(acc[j][1]);
        o.z = flo(acc[j][2]) + fhi(acc[j][2]);
        o.w = flo(acc[j][3]) + fhi(acc[j][3]);
        *reinterpret_cast<float4*>(&g_logits[(size_t)(tb + t0 + j) * E_EXP + e0]) = o;
    }
}

// ---------------------------------------------------------------------------
// Kernel 2: warp per token. softmax over 64, top-2 (jax tie-break: lower index
// first on equal values), renorm softmax of the 2 selected scores.
// ---------------------------------------------------------------------------
__global__ void gate_topk(float* __restrict__ out, int out_size) {
    const int lane = threadIdx.x & 31;
    const int warp = threadIdx.x >> 5;
    const int t = blockIdx.x * 4 + warp;

    const float* lp = g_logits + (size_t)t * E_EXP;
    const float a = lp[lane];
    const float b = lp[lane + 32];

    float v1, v2; int i1, i2;
    if (a >= b) { v1 = a; i1 = lane;      v2 = b; i2 = lane + 32; }
    else        { v1 = b; i1 = lane + 32; v2 = a; i2 = lane;      }

#pragma unroll
    for (int off = 16; off > 0; off >>= 1) {
        float ov1 = __shfl_xor_sync(0xffffffffu, v1, off);
        int   oi1 = __shfl_xor_sync(0xffffffffu, i1, off);
        float ov2 = __shfl_xor_sync(0xffffffffu, v2, off);
        int   oi2 = __shfl_xor_sync(0xffffffffu, i2, off);
        if (ov1 > v1 || (ov1 == v1 && oi1 < i1)) {
            v2 = v1; i2 = i1; v1 = ov1; i1 = oi1;
            if (ov2 > v2 || (ov2 == v2 && oi2 < i2)) { v2 = ov2; i2 = oi2; }
        } else {
            if (ov1 > v2 || (ov1 == v2 && oi1 < i2))      { v2 = ov1; i2 = oi1; }
            else if (ov2 > v2 || (ov2 == v2 && oi2 < i2)) { v2 = ov2; i2 = oi2; }
        }
    }

    // softmax denominator over all 64 (max = v1)
    const float m = v1;
    float ssum = expf(a - m) + expf(b - m);
#pragma unroll
    for (int off = 16; off > 0; off >>= 1)
        ssum += __shfl_xor_sync(0xffffffffu, ssum, off);

    const float invZ = 1.0f / ssum;
    const float s1 = invZ;                  // exp(v1 - m) = 1
    const float s2 = expf(v2 - m) * invZ;

    // renormalizing softmax over [s1, s2], max-subtracted like jax (max = s1)
    const float r  = expf(s2 - s1);
    const float o1 = 1.0f / (1.0f + r);
    const float o2 = r * o1;

    if (lane == 0) {
        out[2 * t]     = o1;
        out[2 * t + 1] = o2;
        out[2 * T_TOKENS + 2 * t]     = (float)i1;
        out[2 * T_TOKENS + 2 * t + 1] = (float)i2;
    }
    // aux_loss = 0.0 and any padding
    if (blockIdx.x == 0) {
        for (int i = 4 * T_TOKENS + (int)threadIdx.x; i < out_size; i += (int)blockDim.x)
            out[i] = 0.0f;
    }
}

extern "C" void kernel_launch(void* const* d_in, const int* in_sizes, int n_in,
                              void* d_out, int out_size) {
    const float* x;
    const float* W;
    // x has T*H = 67,108,864 elems; W has E*H = 262,144. Detect order defensively.
    if (in_sizes[0] == E_EXP * H_DIM && in_sizes[1] != E_EXP * H_DIM) {
        W = (const float*)d_in[0];
        x = (const float*)d_in[1];
    } else {
        x = (const float*)d_in[0];
        W = (const float*)d_in[1];
    }
    float* out = (float*)d_out;

    gate_gemm<<<T_TOKENS / BM, 256>>>(x, W);
    gate_topk<<<T_TOKENS / 4, 128>>>(out, out_size);
}

// round 4
// speedup vs baseline: 1.2546x; 1.2546x over previous
#include <cuda_runtime.h>
#include <cstdint>

// StableMoEGate via 3xTF32 mma.sync (m16n8k8), fused top-2 epilogue.
// out (f32): [scores 2T][idx-as-float 2T][aux 1]

#define T_TOKENS 16384
#define H_DIM    4096
#define E_EXP    64
#define BM       128
#define KC       32
#define NCH      (H_DIM / KC)    // 128
#define RS       36              // padded row stride in words (conflict-free, 16B-aligned)
#define LS       66              // logits smem stride (even -> st.64 aligned)
#define NBUF     3

__device__ float g_Wbig[E_EXP * H_DIM];   // 1 MB
__device__ float g_Wsml[E_EXP * H_DIM];   // 1 MB

__device__ __forceinline__ uint32_t tf32_bits(float a) {
    uint32_t r; asm("cvt.rna.tf32.f32 %0, %1;" : "=r"(r) : "f"(a));
    return r;
}
__device__ __forceinline__ void cp16(void* smem, const void* gmem) {
    unsigned s = (unsigned)__cvta_generic_to_shared(smem);
    asm volatile("cp.async.cg.shared.global [%0], [%1], 16;" :: "r"(s), "l"(gmem));
}
__device__ __forceinline__ void mma_tf32(float* d, const uint32_t* a, const uint32_t* b) {
    asm volatile(
        "mma.sync.aligned.m16n8k8.row.col.f32.tf32.tf32.f32 "
        "{%0,%1,%2,%3}, {%4,%5,%6,%7}, {%8,%9}, {%0,%1,%2,%3};"
        : "+f"(d[0]), "+f"(d[1]), "+f"(d[2]), "+f"(d[3])
        : "r"(a[0]), "r"(a[1]), "r"(a[2]), "r"(a[3]), "r"(b[0]), "r"(b[1]));
}

// ---------------- W split pre-kernel ----------------
__global__ void wsplit(const float* __restrict__ W) {
    int i = blockIdx.x * blockDim.x + threadIdx.x;
    if (i < E_EXP * H_DIM) {
        float w = W[i];
        uint32_t bb = tf32_bits(w);
        float b = __uint_as_float(bb);
        g_Wbig[i] = b;
        g_Wsml[i] = w - b;   // consumed as tf32 (HW truncates low bits; error ~2^-23)
    }
}

// ---------------- main kernel ----------------
__global__ void __launch_bounds__(256, 1)
gate_main(const float* __restrict__ x, float* __restrict__ out, int out_size) {
    extern __shared__ float sm[];
    // layout (words): XS[NBUF][128][RS] then WB[NBUF][2][64][RS]
    float* XS = sm;
    float* WB = sm + NBUF * BM * RS;

    const int tid  = threadIdx.x;
    const int warp = tid >> 5, lane = tid & 31;
    const int grp  = lane >> 2, tig = lane & 3;
    const int wm   = warp & 3;        // token  group *32
    const int wn   = warp >> 2;       // expert group *32
    const int tb   = blockIdx.x * BM;

    float acc[2][4][4];
#pragma unroll
    for (int mt = 0; mt < 2; ++mt)
#pragma unroll
        for (int nt = 0; nt < 4; ++nt)
#pragma unroll
            for (int i = 0; i < 4; ++i) acc[mt][nt][i] = 0.0f;

    // ---- chunk issue: one commit group = x chunk + W(big,small) chunk ----
    auto issue_chunk = [&](int s, int buf) {
#pragma unroll
        for (int r = 0; r < 4; ++r) {                       // x: 1024 x 16B
            int id = tid + 256 * r;
            int row = id >> 3, c4 = id & 7;
            cp16(&XS[(buf * BM + row) * RS + c4 * 4],
                 x + (size_t)(tb + row) * H_DIM + s * KC + c4 * 4);
        }
#pragma unroll
        for (int r = 0; r < 4; ++r) {                       // W: 1024 x 16B (2 parts)
            int id = tid + 256 * r;
            int part = id >> 9, pid = id & 511;
            int e = pid >> 3, c4 = pid & 7;
            const float* src = (part ? g_Wsml : g_Wbig) + (size_t)e * H_DIM + s * KC + c4 * 4;
            cp16(&WB[((buf * 2 + part) * E_EXP + e) * RS + c4 * 4], src);
        }
        asm volatile("cp.async.commit_group;" ::: "memory");
    };

    issue_chunk(0, 0);
    issue_chunk(1, 1);

    for (int s = 0; s < NCH; ++s) {
        const int buf = s % NBUF;
        if (s < NCH - 1) asm volatile("cp.async.wait_group 1;" ::: "memory");
        else             asm volatile("cp.async.wait_group 0;" ::: "memory");
        __syncthreads();
        if (s + 2 < NCH) issue_chunk(s + 2, (s + 2) % NBUF);

        const float* xp = XS + buf * BM * RS + wm * 32 * RS;
        const float* wbg = WB + (buf * 2 + 0) * E_EXP * RS + wn * 32 * RS;
        const float* wsm = WB + (buf * 2 + 1) * E_EXP * RS + wn * 32 * RS;

#pragma unroll
        for (int ks = 0; ks < KC / 8; ++ks) {
            const int kc = ks * 8;
            uint32_t abig[2][4], asml[2][4];
#pragma unroll
            for (int mt = 0; mt < 2; ++mt) {
                const float* rp = xp + (mt * 16 + grp) * RS + kc + tig;
                float r0 = rp[0];
                float r1 = rp[8 * RS];
                float r2 = rp[4];
                float r3 = rp[8 * RS + 4];
                abig[mt][0] = tf32_bits(r0); asml[mt][0] = __float_as_uint(r0 - __uint_as_float(abig[mt][0]));
                abig[mt][1] = tf32_bits(r1); asml[mt][1] = __float_as_uint(r1 - __uint_as_float(abig[mt][1]));
                abig[mt][2] = tf32_bits(r2); asml[mt][2] = __float_as_uint(r2 - __uint_as_float(abig[mt][2]));
                abig[mt][3] = tf32_bits(r3); asml[mt][3] = __float_as_uint(r3 - __uint_as_float(abig[mt][3]));
            }
            uint32_t bbig[4][2], bsml[4][2];
#pragma unroll
            for (int nt = 0; nt < 4; ++nt) {
                const float* bp = wbg + (nt * 8 + grp) * RS + kc + tig;
                bbig[nt][0] = __float_as_uint(bp[0]);
                bbig[nt][1] = __float_as_uint(bp[4]);
                const float* sp = wsm + (nt * 8 + grp) * RS + kc + tig;
                bsml[nt][0] = __float_as_uint(sp[0]);
                bsml[nt][1] = __float_as_uint(sp[4]);
            }
#pragma unroll
            for (int mt = 0; mt < 2; ++mt)
#pragma unroll
                for (int nt = 0; nt < 4; ++nt) {
                    mma_tf32(acc[mt][nt], abig[mt], bbig[nt]);
                    mma_tf32(acc[mt][nt], abig[mt], bsml[nt]);
                    mma_tf32(acc[mt][nt], asml[mt], bbig[nt]);
                }
        }
    }

    // ---- epilogue: logits -> smem, warp-per-token top-2 ----
    __syncthreads();               // all MMA reads of XS done
    float* LG = sm;                // overlay: [128][LS]
#pragma unroll
    for (int mt = 0; mt < 2; ++mt)
#pragma unroll
        for (int nt = 0; nt < 4; ++nt) {
            int r0 = wm * 32 + mt * 16 + grp;
            int c0 = wn * 32 + nt * 8 + tig * 2;
            *reinterpret_cast<float2*>(&LG[r0 * LS + c0]) =
                make_float2(acc[mt][nt][0], acc[mt][nt][1]);
            *reinterpret_cast<float2*>(&LG[(r0 + 8) * LS + c0]) =
                make_float2(acc[mt][nt][2], acc[mt][nt][3]);
        }
    __syncthreads();

    for (int i = 0; i < 16; ++i) {
        const int tl = warp * 16 + i;
        const float a = LG[tl * LS + lane];
        const float b = LG[tl * LS + 32 + lane];

        float v1, v2; int i1, i2;
        if (a >= b) { v1 = a; i1 = lane;      v2 = b; i2 = lane + 32; }
        else        { v1 = b; i1 = lane + 32; v2 = a; i2 = lane;      }
#pragma unroll
        for (int off = 16; off > 0; off >>= 1) {
            float ov1 = __shfl_xor_sync(0xffffffffu, v1, off);
            int   oi1 = __shfl_xor_sync(0xffffffffu, i1, off);
            float ov2 = __shfl_xor_sync(0xffffffffu, v2, off);
            int   oi2 = __shfl_xor_sync(0xffffffffu, i2, off);
            if (ov1 > v1 || (ov1 == v1 && oi1 < i1)) {
                v2 = v1; i2 = i1; v1 = ov1; i1 = oi1;
                if (ov2 > v2 || (ov2 == v2 && oi2 < i2)) { v2 = ov2; i2 = oi2; }
            } else {
                if (ov1 > v2 || (ov1 == v2 && oi1 < i2))      { v2 = ov1; i2 = oi1; }
                else if (ov2 > v2 || (ov2 == v2 && oi2 < i2)) { v2 = ov2; i2 = oi2; }
            }
        }
        const float m = v1;
        float ssum = expf(a - m) + expf(b - m);
#pragma unroll
        for (int off = 16; off > 0; off >>= 1)
            ssum += __shfl_xor_sync(0xffffffffu, ssum, off);

        if (lane == 0) {
            const float invZ = 1.0f / ssum;
            const float s1 = invZ;                    // exp(v1-m)=1
            const float s2 = expf(v2 - m) * invZ;
            const float r  = expf(s2 - s1);           // renorm softmax (max = s1)
            const float o1 = 1.0f / (1.0f + r);
            const float o2 = r * o1;
            const int t = tb + tl;
            out[2 * t]     = o1;
            out[2 * t + 1] = o2;
            out[2 * T_TOKENS + 2 * t]     = (float)i1;
            out[2 * T_TOKENS + 2 * t + 1] = (float)i2;
        }
    }

    if (blockIdx.x == 0) {
        for (int i = 4 * T_TOKENS + tid; i < out_size; i += 256)
            out[i] = 0.0f;
    }
}

extern "C" void kernel_launch(void* const* d_in, const int* in_sizes, int n_in,
                              void* d_out, int out_size) {
    const float* x;
    const float* W;
    if (in_sizes[0] == E_EXP * H_DIM && in_sizes[1] != E_EXP * H_DIM) {
        W = (const float*)d_in[0];
        x = (const float*)d_in[1];
    } else {
        x = (const float*)d_in[0];
        W = (const float*)d_in[1];
    }
    float* out = (float*)d_out;

    const int SMEM = (NBUF * BM * RS + NBUF * 2 * E_EXP * RS) * 4;   // 110,592 B
    cudaFuncSetAttribute(gate_main, cudaFuncAttributeMaxDynamicSharedMemorySize, SMEM);

    wsplit<<<(E_EXP * H_DIM + 255) / 256, 256>>>(W);
    gate_main<<<T_TOKENS / BM, 256, SMEM>>>(x, out, out_size);
}

// round 6
// speedup vs baseline: 1.3728x; 1.0943x over previous
#include <cuda_runtime.h>
#include <cstdint>

// StableMoEGate via 3xTF32 mma.sync (m16n8k8), K-split 2, fused combine+top-2.
// out (f32): [scores 2T][idx-as-float 2T][aux 1]

#define T_TOKENS 16384
#define H_DIM    4096
#define E_EXP    64
#define BM       128
#define KC       32
#define KHALF    (H_DIM / 2)     // 2048
#define NCH      (KHALF / KC)    // 64 chunks per CTA
#define RS       36              // padded row stride (words)
#define NBUF     3

__device__ float g_Wbig[E_EXP * H_DIM];            // 1 MB
__device__ float g_Wsml[E_EXP * H_DIM];            // 1 MB
__device__ float g_part0[T_TOKENS * E_EXP];        // 4 MB partial (K half 0)
__device__ float g_part1[T_TOKENS * E_EXP];        // 4 MB partial (K half 1)

__device__ __forceinline__ uint32_t tf32_bits(float a) {
    uint32_t r; asm("cvt.rna.tf32.f32 %0, %1;" : "=r"(r) : "f"(a));
    return r;
}
__device__ __forceinline__ void cp16(void* smem, const void* gmem) {
    unsigned s = (unsigned)__cvta_generic_to_shared(smem);
    asm volatile("cp.async.cg.shared.global [%0], [%1], 16;" :: "r"(s), "l"(gmem));
}
__device__ __forceinline__ void mma_tf32(float* d, const uint32_t* a, const uint32_t* b) {
    asm volatile(
        "mma.sync.aligned.m16n8k8.row.col.f32.tf32.tf32.f32 "
        "{%0,%1,%2,%3}, {%4,%5,%6,%7}, {%8,%9}, {%0,%1,%2,%3};"
        : "+f"(d[0]), "+f"(d[1]), "+f"(d[2]), "+f"(d[3])
        : "r"(a[0]), "r"(a[1]), "r"(a[2]), "r"(a[3]), "r"(b[0]), "r"(b[1]));
}

// ---------------- W split pre-kernel ----------------
__global__ void wsplit(const float* __restrict__ W) {
    int i = blockIdx.x * blockDim.x + threadIdx.x;
    if (i < E_EXP * H_DIM) {
        float w = W[i];
        float b = __uint_as_float(tf32_bits(w));
        g_Wbig[i] = b;
        g_Wsml[i] = w - b;   // consumed as tf32 (residual ~2^-23)
    }
}

// ---------------- GEMM kernel: one CTA = 128 tokens x 64 experts x K-half ----
__global__ void __launch_bounds__(256, 2)
gate_gemm(const float* __restrict__ x) {
    extern __shared__ float sm[];
    float* XS = sm;                       // [NBUF][128][RS]
    float* WB = sm + NBUF * BM * RS;      // [NBUF][2][64][RS]

    const int tid  = threadIdx.x;
    const int warp = tid >> 5, lane = tid & 31;
    const int grp  = lane >> 2, tig = lane & 3;
    const int wm   = warp & 3;            // token  group *32
    const int wn   = warp >> 2;           // expert group *32
    const int tile = blockIdx.x >> 1;
    const int kh   = blockIdx.x & 1;
    const int tb   = tile * BM;
    const int k0   = kh * KHALF;
    float* gpart   = kh ? g_part1 : g_part0;

    float acc[2][4][4];
#pragma unroll
    for (int mt = 0; mt < 2; ++mt)
#pragma unroll
        for (int nt = 0; nt < 4; ++nt)
#pragma unroll
            for (int i = 0; i < 4; ++i) acc[mt][nt][i] = 0.0f;

    auto issue_chunk = [&](int s, int buf) {
        const int koff = k0 + s * KC;
#pragma unroll
        for (int r = 0; r < 4; ++r) {                       // x: 1024 x 16B
            int id = tid + 256 * r;
            int row = id >> 3, c4 = id & 7;
            cp16(&XS[(buf * BM + row) * RS + c4 * 4],
                 x + (size_t)(tb + row) * H_DIM + koff + c4 * 4);
        }
#pragma unroll
        for (int r = 0; r < 4; ++r) {                       // W: 1024 x 16B (2 parts)
            int id = tid + 256 * r;
            int part = id >> 9, pid = id & 511;
            int e = pid >> 3, c4 = pid & 7;
            const float* src = (part ? g_Wsml : g_Wbig) + (size_t)e * H_DIM + koff + c4 * 4;
            cp16(&WB[((buf * 2 + part) * E_EXP + e) * RS + c4 * 4], src);
        }
        asm volatile("cp.async.commit_group;" ::: "memory");
    };

    issue_chunk(0, 0);
    issue_chunk(1, 1);

    for (int s = 0; s < NCH; ++s) {
        const int buf = s % NBUF;
        if (s < NCH - 1) asm volatile("cp.async.wait_group 1;" ::: "memory");
        else             asm volatile("cp.async.wait_group 0;" ::: "memory");
        __syncthreads();
        if (s + 2 < NCH) issue_chunk(s + 2, (s + 2) % NBUF);

        const float* xp  = XS + buf * BM * RS + wm * 32 * RS;
        const float* wbg = WB + (buf * 2 + 0) * E_EXP * RS + wn * 32 * RS;
        const float* wsm = WB + (buf * 2 + 1) * E_EXP * RS + wn * 32 * RS;

#pragma unroll
        for (int ks = 0; ks < KC / 8; ++ks) {
            const int kc = ks * 8;
            uint32_t abig[2][4], asml[2][4];
#pragma unroll
            for (int mt = 0; mt < 2; ++mt) {
                const float* rp = xp + (mt * 16 + grp) * RS + kc + tig;
                float r0 = rp[0];
                float r1 = rp[8 * RS];
                float r2 = rp[4];
                float r3 = rp[8 * RS + 4];
                abig[mt][0] = tf32_bits(r0); asml[mt][0] = __float_as_uint(r0 - __uint_as_float(abig[mt][0]));
                abig[mt][1] = tf32_bits(r1); asml[mt][1] = __float_as_uint(r1 - __uint_as_float(abig[mt][1]));
                abig[mt][2] = tf32_bits(r2); asml[mt][2] = __float_as_uint(r2 - __uint_as_float(abig[mt][2]));
                abig[mt][3] = tf32_bits(r3); asml[mt][3] = __float_as_uint(r3 - __uint_as_float(abig[mt][3]));
            }
            uint32_t bbig[4][2], bsml[4][2];
#pragma unroll
            for (int nt = 0; nt < 4; ++nt) {
                const float* bp = wbg + (nt * 8 + grp) * RS + kc + tig;
                bbig[nt][0] = __float_as_uint(bp[0]);
                bbig[nt][1] = __float_as_uint(bp[4]);
                const float* sp = wsm + (nt * 8 + grp) * RS + kc + tig;
                bsml[nt][0] = __float_as_uint(sp[0]);
                bsml[nt][1] = __float_as_uint(sp[4]);
            }
            // pass-major: 8 independent MMAs between each RAW reuse of an accumulator
#pragma unroll
            for (int mt = 0; mt < 2; ++mt)
#pragma unroll
                for (int nt = 0; nt < 4; ++nt)
                    mma_tf32(acc[mt][nt], abig[mt], bbig[nt]);
#pragma unroll
            for (int mt = 0; mt < 2; ++mt)
#pragma unroll
                for (int nt = 0; nt < 4; ++nt)
                    mma_tf32(acc[mt][nt], abig[mt], bsml[nt]);
#pragma unroll
            for (int mt = 0; mt < 2; ++mt)
#pragma unroll
                for (int nt = 0; nt < 4; ++nt)
                    mma_tf32(acc[mt][nt], asml[mt], bbig[nt]);
        }
    }

    // write partial logits [token][expert]
#pragma unroll
    for (int mt = 0; mt < 2; ++mt)
#pragma unroll
        for (int nt = 0; nt < 4; ++nt) {
            int r0 = tb + wm * 32 + mt * 16 + grp;
            int c0 = wn * 32 + nt * 8 + tig * 2;
            *reinterpret_cast<float2*>(&gpart[(size_t)r0 * E_EXP + c0]) =
                make_float2(acc[mt][nt][0], acc[mt][nt][1]);
            *reinterpret_cast<float2*>(&gpart[(size_t)(r0 + 8) * E_EXP + c0]) =
                make_float2(acc[mt][nt][2], acc[mt][nt][3]);
        }
}

// ---------------- combine + top-2 kernel: warp per token ----------------
__global__ void __launch_bounds__(256)
gate_combine(float* __restrict__ out, int out_size) {
    const int lane = threadIdx.x & 31;
    const int warp = threadIdx.x >> 5;
    const int t = blockIdx.x * 8 + warp;

    const float2* p0 = reinterpret_cast<const float2*>(g_part0 + (size_t)t * E_EXP);
    const float2* p1 = reinterpret_cast<const float2*>(g_part1 + (size_t)t * E_EXP);
    float2 a = p0[lane], b = p1[lane];
    const float e0 = a.x + b.x;
    const float e1 = a.y + b.y;
    const int j0 = 2 * lane, j1 = 2 * lane + 1;

    float v1, v2; int i1, i2;
    if (e0 >= e1) { v1 = e0; i1 = j0; v2 = e1; i2 = j1; }
    else          { v1 = e1; i1 = j1; v2 = e0; i2 = j0; }

#pragma unroll
    for (int off = 16; off > 0; off >>= 1) {
        float ov1 = __shfl_xor_sync(0xffffffffu, v1, off);
        int   oi1 = __shfl_xor_sync(0xffffffffu, i1, off);
        float ov2 = __shfl_xor_sync(0xffffffffu, v2, off);
        int   oi2 = __shfl_xor_sync(0xffffffffu, i2, off);
        if (ov1 > v1 || (ov1 == v1 && oi1 < i1)) {
            v2 = v1; i2 = i1; v1 = ov1; i1 = oi1;
            if (ov2 > v2 || (ov2 == v2 && oi2 < i2)) { v2 = ov2; i2 = oi2; }
        } else {
            if (ov1 > v2 || (ov1 == v2 && oi1 < i2))      { v2 = ov1; i2 = oi1; }
            else if (ov2 > v2 || (ov2 == v2 && oi2 < i2)) { v2 = ov2; i2 = oi2; }
        }
    }

    const float m = v1;
    float ssum = expf(e0 - m) + expf(e1 - m);
#pragma unroll
    for (int off = 16; off > 0; off >>= 1)
        ssum += __shfl_xor_sync(0xffffffffu, ssum, off);

    if (lane == 0) {
        const float invZ = 1.0f / ssum;
        const float s1 = invZ;                    // exp(v1-m)=1
        const float s2 = expf(v2 - m) * invZ;
        const float r  = expf(s2 - s1);           // renorm softmax (max = s1)
        const float o1 = 1.0f / (1.0f + r);
        const float o2 = r * o1;
        out[2 * t]     = o1;
        out[2 * t + 1] = o2;
        out[2 * T_TOKENS + 2 * t]     = (float)i1;
        out[2 * T_TOKENS + 2 * t + 1] = (float)i2;
    }
    if (blockIdx.x == 0) {
        for (int i = 4 * T_TOKENS + (int)threadIdx.x; i < out_size; i += 256)
            out[i] = 0.0f;
    }
}

extern "C" void kernel_launch(void* const* d_in, const int* in_sizes, int n_in,
                              void* d_out, int out_size) {
    const float* x;
    const float* W;
    if (in_sizes[0] == E_EXP * H_DIM && in_sizes[1] != E_EXP * H_DIM) {
        W = (const float*)d_in[0];
        x = (const float*)d_in[1];
    } else {
        x = (const float*)d_in[0];
        W = (const float*)d_in[1];
    }
    float* out = (float*)d_out;

    const int SMEM = (NBUF * BM * RS + NBUF * 2 * E_EXP * RS) * 4;   // 110,592 B
    cudaFuncSetAttribute(gate_gemm, cudaFuncAttributeMaxDynamicSharedMemorySize, SMEM);

    wsplit<<<(E_EXP * H_DIM + 255) / 256, 256>>>(W);
    gate_gemm<<<(T_TOKENS / BM) * 2, 256, SMEM>>>(x);
    gate_combine<<<T_TOKENS / 8, 256>>>(out, out_size);
}